// round 3
// baseline (speedup 1.0000x reference)
#include <cuda_runtime.h>
#include <cstdint>

// ---------------------------------------------------------------------------
// DifferentiableBiquadChain: 16 cascaded SVF biquads, per-frame coefficients.
//
// Block = (batch b, frame f), 128 threads x 16 samples each.
// Per filter: zero-state segment sim -> affine scan (constant-A per frame,
// matrix powers built by repeated squaring) -> cross-frame state via
// wavefront publish/spin (64-bit relaxed atomics, NaN sentinel) -> exact
// re-simulation with reference arithmetic. Audio stays in registers across
// all 16 filter stages.
// ---------------------------------------------------------------------------

#define NB      16
#define FRAME   2048
#define NFR     24
#define BATCH   32
#define TPB     128
#define SPT     16
#define SVAL    0xFFFFFFFFFFFFFFFFull

__device__ unsigned long long g_state[BATCH * NFR * NB];

__global__ void init_state_kernel() {
    int i = blockIdx.x * blockDim.x + threadIdx.x;
    if (i < BATCH * NFR * NB) g_state[i] = SVAL;
}

struct M2 { float a, b, c, d; }; // [[a,b],[c,d]]

__device__ __forceinline__ M2 msq(M2 m) {
    M2 r;
    float apd = m.a + m.d;
    r.a = fmaf(m.a, m.a, m.b * m.c);
    r.b = m.b * apd;
    r.c = m.c * apd;
    r.d = fmaf(m.d, m.d, m.b * m.c);
    return r;
}

__device__ __forceinline__ M2 mmul(M2 p, M2 q) {
    M2 r;
    r.a = fmaf(p.a, q.a, p.b * q.c);
    r.b = fmaf(p.a, q.b, p.b * q.d);
    r.c = fmaf(p.c, q.a, p.d * q.c);
    r.d = fmaf(p.c, q.b, p.d * q.d);
    return r;
}

__device__ __forceinline__ unsigned long long ld_relaxed_u64(const unsigned long long* p) {
    unsigned long long v;
    asm volatile("ld.relaxed.gpu.global.u64 %0, [%1];" : "=l"(v) : "l"(p) : "memory");
    return v;
}
__device__ __forceinline__ void st_relaxed_u64(unsigned long long* p, unsigned long long v) {
    asm volatile("st.relaxed.gpu.global.u64 [%0], %1;" : : "l"(p), "l"(v) : "memory");
}

__global__ __launch_bounds__(TPB, 6)
void eq_kernel(const float* __restrict__ audio,
               const float* __restrict__ params,
               float* __restrict__ out)
{
    const int blk  = blockIdx.x;
    const int f    = blk >> 5;   // frame (f-major: predecessors have lower blockIdx)
    const int b    = blk & 31;   // batch
    const int t    = threadIdx.x;
    const int lane = t & 31;
    const int w    = t >> 5;

    __shared__ float cf[NB][6];     // a1 a2 a3 m0 m1 m2
    __shared__ float sh_gain[2];    // in_g, out_g
    __shared__ float shT[4][2];     // warp totals
    __shared__ float sh_sin[2];     // frame incoming state

    // ---------------- coefficients (threads 0..17) ----------------
    if (t < NB) {
        const float* pb = params + (size_t)(b * 50) * NFR + f;
        float fn = pb[(t * 3 + 0) * NFR];
        float gn = pb[(t * 3 + 1) * NFR];
        float qn = pb[(t * 3 + 2) * NFR];

        // Q = exp(ln0.5 + qn*(ln16 - ln0.5)), clip [0.1, 100]
        float Q = expf(fmaf(qn, 3.4657359f, -0.6931472f));
        Q = fminf(fmaxf(Q, 0.1f), 100.0f);

        float gain = fmaf(gn, 48.0f, -24.0f);
        float A  = exp10f(gain * 0.025f);   // 10^(gain/40)
        float sA = sqrtf(A);

        float lnlo, lnhi;
        if      (t == 0)            { lnlo = 2.9957323f; lnhi = 6.2146081f; } // HPF 20..500
        else if (t == 15)           { lnlo = 8.5171932f; lnhi = 9.9034876f; } // LPF 5k..20k
        else if (t == 1 || t == 14) { lnlo = 3.9120230f; lnhi = 9.6803184f; } // shelf 50..16k
        else                        { lnlo = 4.6051702f; lnhi = 9.6158055f; } // peak 100..15k
        float fc = expf(fmaf(fn, (lnhi - lnlo), lnlo));
        float g  = tanf(fc * 3.27249235e-5f);           // tan(pi*fc/96000)
        g = fminf(fmaxf(g, 1e-6f), 100.0f);

        float a1, a2, a3, m0, m1, m2;
        if (t == 0) {            // highpass
            float k = 1.0f / Q;
            a1 = 1.0f / (1.0f + g * (g + k)); a2 = g * a1; a3 = g * a2;
            m0 = 1.0f; m1 = -k; m2 = -1.0f;
        } else if (t == 15) {    // lowpass
            float k = 1.0f / Q;
            a1 = 1.0f / (1.0f + g * (g + k)); a2 = g * a1; a3 = g * a2;
            m0 = 0.0f; m1 = 0.0f; m2 = 1.0f;
        } else if (t == 1) {     // lowshelf
            float k = 1.0f / Q;
            float gs = (gain >= 0.0f) ? (g / sA) : (g * sA);
            a1 = 1.0f / (1.0f + gs * (gs + k)); a2 = gs * a1; a3 = gs * a2;
            m0 = 1.0f; m1 = k * (A - 1.0f); m2 = A * A - 1.0f;
        } else if (t == 14) {    // highshelf
            float k = 1.0f / Q;
            float gs = (gain >= 0.0f) ? (g * sA) : (g / sA);
            a1 = 1.0f / (1.0f + gs * (gs + k)); a2 = gs * a1; a3 = gs * a2;
            m0 = A * A; m1 = k * (1.0f - A) * A; m2 = 1.0f - A * A;
        } else {                 // peak
            float k = (gain >= 0.0f) ? (1.0f / (Q * A)) : (A / Q);
            a1 = 1.0f / (1.0f + g * (g + k)); a2 = g * a1; a3 = g * a2;
            m0 = 1.0f; m1 = k * (A * A - 1.0f); m2 = 0.0f;
        }
        cf[t][0] = a1; cf[t][1] = a2; cf[t][2] = a3;
        cf[t][3] = m0; cf[t][4] = m1; cf[t][5] = m2;
    } else if (t == 16 || t == 17) {
        float n  = params[(size_t)(b * 50 + 48 + (t - 16)) * NFR + f];
        float db = fmaf(n, 60.0f, -60.0f);
        sh_gain[t - 16] = exp10f(db * 0.05f);  // 10^(db/20)
    }
    __syncthreads();

    // ---------------- load audio (x stays in registers) ----------------
    const float ing  = sh_gain[0];
    const float outg = sh_gain[1];
    float x[SPT];
    {
        const float4* ap = (const float4*)(audio + (size_t)b * 49152 + f * FRAME + t * SPT);
        #pragma unroll
        for (int j = 0; j < 4; j++) {
            float4 v = ap[j];
            x[4 * j + 0] = v.x * ing;
            x[4 * j + 1] = v.y * ing;
            x[4 * j + 2] = v.z * ing;
            x[4 * j + 3] = v.w * ing;
        }
    }

    // ---------------- filter cascade ----------------
    for (int i = 0; i < NB; i++) {
        const float a1 = cf[i][0], a2 = cf[i][1], a3 = cf[i][2];
        const float m0 = cf[i][3], m1 = cf[i][4], m2 = cf[i][5];

        // zero-state sim over this thread's 16 samples -> segment offset (c1,c2)
        float c1 = 0.0f, c2 = 0.0f;
        #pragma unroll
        for (int j = 0; j < SPT; j++) {
            float v3 = x[j] - c2;
            float v1 = fmaf(a1, c1, a2 * v3);
            float v2 = fmaf(a2, v1, fmaf(a3, v3, c2));
            c1 = fmaf(2.0f, v1, -c1);
            c2 = fmaf(2.0f, v2, -c2);
        }

        // state transition A, then A^16
        M2 M;
        M.a = fmaf(2.0f, a1, -1.0f);
        M.b = -2.0f * a2;
        M.c = 2.0f * a1 * a2;
        M.d = 1.0f - 2.0f * fmaf(a2, a2, a3);
        M = msq(msq(msq(msq(M))));  // A^16

        // warp affine scan; simultaneously build L = A^(16*lane)
        M2 L; L.a = 1.0f; L.b = 0.0f; L.c = 0.0f; L.d = 1.0f;
        #pragma unroll
        for (int k = 0; k < 5; k++) {
            float o1 = __shfl_up_sync(0xFFFFFFFFu, c1, 1 << k);
            float o2 = __shfl_up_sync(0xFFFFFFFFu, c2, 1 << k);
            if (lane >= (1 << k)) {
                c1 = fmaf(M.a, o1, fmaf(M.b, o2, c1));
                c2 = fmaf(M.c, o1, fmaf(M.d, o2, c2));
            }
            if (lane & (1 << k)) L = mmul(M, L);
            M = msq(M);             // after loop: M = A^512
        }

        // within-warp exclusive offset
        float e1 = __shfl_up_sync(0xFFFFFFFFu, c1, 1);
        float e2 = __shfl_up_sync(0xFFFFFFFFu, c2, 1);
        if (lane == 0) { e1 = 0.0f; e2 = 0.0f; }

        if (lane == 31) { shT[w][0] = c1; shT[w][1] = c2; }
        __syncthreads();

        float Ta[4], Tb[4];
        #pragma unroll
        for (int j = 0; j < 4; j++) { Ta[j] = shT[j][0]; Tb[j] = shT[j][1]; }

        // thread 0: obtain frame-in state, publish frame-out state ASAP
        if (t == 0) {
            float si1 = 0.0f, si2 = 0.0f;
            if (f > 0) {
                const unsigned long long* src =
                    &g_state[((size_t)b * NFR + (f - 1)) * NB + i];
                unsigned long long v = ld_relaxed_u64(src);
                while (v == SVAL) { __nanosleep(32); v = ld_relaxed_u64(src); }
                si1 = __uint_as_float((unsigned)(v & 0xFFFFFFFFu));
                si2 = __uint_as_float((unsigned)(v >> 32));
            }
            if (f < NFR - 1) {
                float S1 = si1, S2 = si2;
                #pragma unroll
                for (int j = 0; j < 4; j++) {
                    float n1 = fmaf(M.a, S1, fmaf(M.b, S2, Ta[j]));
                    float n2 = fmaf(M.c, S1, fmaf(M.d, S2, Tb[j]));
                    S1 = n1; S2 = n2;
                }
                unsigned long long pv =
                    ((unsigned long long)__float_as_uint(S2) << 32) |
                    (unsigned long long)__float_as_uint(S1);
                st_relaxed_u64(&g_state[((size_t)b * NFR + f) * NB + i], pv);
            }
            sh_sin[0] = si1; sh_sin[1] = si2;
        }
        __syncthreads();

        // warp-in state S_w = A^(512w)*s_in + E_w (serial chain, <=3 mat-vecs)
        float S1 = sh_sin[0], S2 = sh_sin[1];
        #pragma unroll
        for (int j = 0; j < 3; j++) {
            if (j < w) {
                float n1 = fmaf(M.a, S1, fmaf(M.b, S2, Ta[j]));
                float n2 = fmaf(M.c, S1, fmaf(M.d, S2, Tb[j]));
                S1 = n1; S2 = n2;
            }
        }

        // thread-in state = L * S_w + e
        float s1 = fmaf(L.a, S1, fmaf(L.b, S2, e1));
        float s2 = fmaf(L.c, S1, fmaf(L.d, S2, e2));

        // exact re-simulation producing outputs (reference arithmetic)
        #pragma unroll
        for (int j = 0; j < SPT; j++) {
            float xn = x[j];
            float v3 = xn - s2;
            float v1 = fmaf(a1, s1, a2 * v3);
            float v2 = fmaf(a2, v1, fmaf(a3, v3, s2));
            x[j] = fmaf(m0, xn, fmaf(m1, v1, m2 * v2));
            s1 = fmaf(2.0f, v1, -s1);
            s2 = fmaf(2.0f, v2, -s2);
        }
    }

    // ---------------- store output ----------------
    {
        float4* op = (float4*)(out + (size_t)b * 49152 + f * FRAME + t * SPT);
        #pragma unroll
        for (int j = 0; j < 4; j++) {
            float4 v;
            v.x = x[4 * j + 0] * outg;
            v.y = x[4 * j + 1] * outg;
            v.z = x[4 * j + 2] * outg;
            v.w = x[4 * j + 3] * outg;
            op[j] = v;
        }
    }
}

extern "C" void kernel_launch(void* const* d_in, const int* in_sizes, int n_in,
                              void* d_out, int out_size) {
    const float* audio;
    const float* params;
    if (in_sizes[0] > in_sizes[1]) { audio = (const float*)d_in[0]; params = (const float*)d_in[1]; }
    else                           { audio = (const float*)d_in[1]; params = (const float*)d_in[0]; }
    float* out = (float*)d_out;

    init_state_kernel<<<(BATCH * NFR * NB + 255) / 256, 256>>>();
    eq_kernel<<<BATCH * NFR, TPB>>>(audio, params, out);
}